// round 9
// baseline (speedup 1.0000x reference)
#include <cuda_runtime.h>
#include <cstdint>

#define NBATCH 512
#define TSTEPS 128
#define NS 32
#define NC 16
#define NSC 48
typedef unsigned long long u64;

__device__ float g_K[(size_t)TSTEPS * NBATCH * NC * NS];
__device__ float g_k[(size_t)TSTEPS * NBATCH * NC];

__device__ __forceinline__ u64 ffma2(u64 a, u64 b, u64 c) {
    u64 d; asm("fma.rn.f32x2 %0,%1,%2,%3;" : "=l"(d) : "l"(a), "l"(b), "l"(c)); return d;
}
__device__ __forceinline__ float lohi(u64 v) {
    float lo, hi; asm("mov.b64 {%0,%1},%2;" : "=f"(lo), "=f"(hi) : "l"(v)); return lo + hi;
}
__device__ __forceinline__ u64 pklo(float lo) {
    u64 d; asm("mov.b64 %0,{%1,%2};" : "=l"(d) : "f"(lo), "f"(0.0f)); return d;
}
__device__ __forceinline__ u64 ld64(const float* p) { return *reinterpret_cast<const u64*>(p); }
// 128-bit shared load as a REAL memory read (compiler-ordered vs barriers/STS).
__device__ __forceinline__ void ld128(const float* p, u64& x, u64& y) {
    ulonglong2 v = *reinterpret_cast<const ulonglong2*>(p);
    x = v.x; y = v.y;
}
__device__ __forceinline__ void cpa16(void* s, const void* g) {
    unsigned sa = (unsigned)__cvta_generic_to_shared(s);
    asm volatile("cp.async.ca.shared.global [%0], [%1], 16;" :: "r"(sa), "l"(g));
}
__device__ __forceinline__ void cpcommit() { asm volatile("cp.async.commit_group;"); }
__device__ __forceinline__ void cpwait0() { asm volatile("cp.async.wait_group 0;"); }
__device__ __forceinline__ void cpwait1() { asm volatile("cp.async.wait_group 1;"); }

#define SF 36
#define SQ 52
#define SX 20

__global__ void lqr_dummy_kernel() {}

// ---------------------------------------------------------------------------
// Backward Riccati pass + analytic cost. One CTA per batch, 256 threads.
// ---------------------------------------------------------------------------
__global__ __launch_bounds__(256, 4)
void lqr_bwd_kernel(const float* __restrict__ Q, const float* __restrict__ p,
                    const float* __restrict__ A, const float* __restrict__ Bm,
                    const float* __restrict__ c1, const float* __restrict__ x_init,
                    float* __restrict__ out)
{
    __shared__ __align__(16) float FkT[NSC * SF];     // FkT[j][k] = F[k][j]
    __shared__ __align__(16) float WkT[NSC * SF];     // WkT[j][k] = (V F)[k][j]
    __shared__ __align__(16) float Vs[NS * SF];       // V row-major
    __shared__ __align__(16) float Qts[NSC * SQ];     // Qt (lower tiles valid)
    __shared__ __align__(16) float Qstage[NSC * NSC]; // raw Q[t] staged
    __shared__ __align__(16) float pstage[NSC];       // raw p[t] staged
    __shared__ __align__(16) float QuxT[NS * SX];     // QuxT[j][u] = Qux[u][j]
    __shared__ __align__(16) float Qinv[NC * SX];
    __shared__ __align__(16) float KT[NS * SX];       // KT[j][r] = K[r][j]
    __shared__ __align__(16) float qts[NSC + 4];
    __shared__ __align__(16) float kts[NC];
    __shared__ __align__(16) float w2[NS];
    __shared__ __align__(16) float vs[NS];
    __shared__ __align__(16) float c1s[NS];
    __shared__ __align__(16) float x0s[NS];
    __shared__ float sred[8];
    __shared__ float sred_c1;
    __shared__ float s_sh;

    const int b = blockIdx.x, tid = threadIdx.x;
    const int lane = tid & 31, wid = tid >> 5;
    const int ty = tid >> 4, tx = tid & 15;
    const bool lowB = (tx <= ty);
    const size_t cBase = (size_t)NBATCH * TSTEPS * NS + (size_t)NBATCH * TSTEPS * NC;

    for (int o = tid; o < NS * NSC; o += 256) {
        int j = o >> 5, k = o & 31;
        FkT[j * SF + k] = (j < NS) ? A[b * NS * NS + k * NS + j]
                                   : Bm[b * NS * NC + k * NC + (j - NS)];
    }
    if (tid < NS) {
        c1s[tid] = c1[b * NS + tid];
        x0s[tid] = x_init[b * NS + tid];
        vs[tid] = 0.f;
    }
    if (tid == 0) s_sh = 0.f;
    for (int o = tid; o < NS * SF; o += 256) Vs[o] = 0.f;

    // stage Q[127], p[127]
    {
        const float* Qg = Q + ((size_t)(b * TSTEPS + TSTEPS - 1)) * (NSC * NSC);
        for (int o = tid; o < 576; o += 256) cpa16(&Qstage[4 * o], Qg + 4 * o);
        if (tid < 12) cpa16(&pstage[4 * tid], p + ((size_t)(b * TSTEPS + TSTEPS - 1)) * NSC + 4 * tid);
        cpcommit();
    }
    __syncthreads();

    const float c1l = c1s[lane];

    for (int t = TSTEPS - 1; t >= 0; --t) {
        // --- Phase A: W = V*F (2x3 tiles, ld128) ; w2 = v + V c1 ---
        {
            u64 a00 = 0, a01 = 0, a02 = 0, a10 = 0, a11 = 0, a12 = 0;
            const float* vr0 = &Vs[(2 * ty) * SF];
            const float* vr1 = vr0 + SF;
            const float* f0 = &FkT[(3 * tx) * SF];
            const float* f1 = f0 + SF;
            const float* f2 = f1 + SF;
#pragma unroll
            for (int kp = 0; kp < 8; ++kp) {
                u64 p0a, p0b, p1a, p1b, p2a, p2b, v0a, v0b, v1a, v1b;
                ld128(f0 + 4 * kp, p0a, p0b);
                ld128(f1 + 4 * kp, p1a, p1b);
                ld128(f2 + 4 * kp, p2a, p2b);
                ld128(vr0 + 4 * kp, v0a, v0b);
                ld128(vr1 + 4 * kp, v1a, v1b);
                a00 = ffma2(v0a, p0a, a00); a00 = ffma2(v0b, p0b, a00);
                a01 = ffma2(v0a, p1a, a01); a01 = ffma2(v0b, p1b, a01);
                a02 = ffma2(v0a, p2a, a02); a02 = ffma2(v0b, p2b, a02);
                a10 = ffma2(v1a, p0a, a10); a10 = ffma2(v1b, p0b, a10);
                a11 = ffma2(v1a, p1a, a11); a11 = ffma2(v1b, p1b, a11);
                a12 = ffma2(v1a, p2a, a12); a12 = ffma2(v1b, p2b, a12);
            }
            WkT[(3 * tx) * SF + 2 * ty] = lohi(a00);
            WkT[(3 * tx + 1) * SF + 2 * ty] = lohi(a01);
            WkT[(3 * tx + 2) * SF + 2 * ty] = lohi(a02);
            WkT[(3 * tx) * SF + 2 * ty + 1] = lohi(a10);
            WkT[(3 * tx + 1) * SF + 2 * ty + 1] = lohi(a11);
            WkT[(3 * tx + 2) * SF + 2 * ty + 1] = lohi(a12);
        }
#pragma unroll
        for (int r = 0; r < 4; ++r) {
            int i = 4 * wid + r;
            float t0 = Vs[i * SF + lane] * c1l;
#pragma unroll
            for (int s = 16; s; s >>= 1) t0 += __shfl_xor_sync(0xffffffffu, t0, s);
            if (lane == 0) w2[i] = vs[i] + t0;
        }
        cpwait0();
        __syncthreads();

        // --- Phase B (lower tiles): Qt = Qstage + F^T W ; qt ; QuxT copy ---
        if (lowB) {
            u64 acc[3][3] = {{0,0,0},{0,0,0},{0,0,0}};
            const float* fr0 = &FkT[(3 * ty) * SF];
            const float* fr1 = fr0 + SF;
            const float* fr2 = fr1 + SF;
            const float* wc0 = &WkT[(3 * tx) * SF];
            const float* wc1 = wc0 + SF;
            const float* wc2 = wc1 + SF;
#pragma unroll
            for (int kp = 0; kp < 8; ++kp) {
                u64 fa0, fa1, fb0, fb1, fc0, fc1;
                u64 w0a, w0b, w1a, w1b, w2a, w2b;
                ld128(fr0 + 4 * kp, fa0, fa1);
                ld128(fr1 + 4 * kp, fb0, fb1);
                ld128(fr2 + 4 * kp, fc0, fc1);
                ld128(wc0 + 4 * kp, w0a, w0b);
                ld128(wc1 + 4 * kp, w1a, w1b);
                ld128(wc2 + 4 * kp, w2a, w2b);
                acc[0][0] = ffma2(fa0, w0a, acc[0][0]); acc[0][0] = ffma2(fa1, w0b, acc[0][0]);
                acc[0][1] = ffma2(fa0, w1a, acc[0][1]); acc[0][1] = ffma2(fa1, w1b, acc[0][1]);
                acc[0][2] = ffma2(fa0, w2a, acc[0][2]); acc[0][2] = ffma2(fa1, w2b, acc[0][2]);
                acc[1][0] = ffma2(fb0, w0a, acc[1][0]); acc[1][0] = ffma2(fb1, w0b, acc[1][0]);
                acc[1][1] = ffma2(fb0, w1a, acc[1][1]); acc[1][1] = ffma2(fb1, w1b, acc[1][1]);
                acc[1][2] = ffma2(fb0, w2a, acc[1][2]); acc[1][2] = ffma2(fb1, w2b, acc[1][2]);
                acc[2][0] = ffma2(fc0, w0a, acc[2][0]); acc[2][0] = ffma2(fc1, w0b, acc[2][0]);
                acc[2][1] = ffma2(fc0, w1a, acc[2][1]); acc[2][1] = ffma2(fc1, w1b, acc[2][1]);
                acc[2][2] = ffma2(fc0, w2a, acc[2][2]); acc[2][2] = ffma2(fc1, w2b, acc[2][2]);
            }
#pragma unroll
            for (int r = 0; r < 3; ++r)
#pragma unroll
                for (int c = 0; c < 3; ++c) {
                    int i = 3 * ty + r, j = 3 * tx + c;
                    float val = Qstage[i * NSC + j] + lohi(acc[r][c]);
                    Qts[i * SQ + j] = val;
                    if (i >= NS && j < NS) QuxT[j * SX + (i - NS)] = val;
                }
        }
        if (tid < NSC) {
            u64 acc = 0;
            const float* fr = &FkT[tid * SF];
#pragma unroll
            for (int kp = 0; kp < 16; ++kp) acc = ffma2(ld64(fr + 2 * kp), ld64(&w2[2 * kp]), acc);
            qts[tid] = pstage[tid] + lohi(acc);
        }
        __syncthreads();

        // --- Phase C: prefetch Q[t-1],p[t-1] ; warp0 inverts Quu ; warp1 c1-dot ---
        if (t > 0) {
            const float* Qg = Q + ((size_t)(b * TSTEPS + t - 1)) * (NSC * NSC);
            for (int o = tid; o < 576; o += 256) cpa16(&Qstage[4 * o], Qg + 4 * o);
            if (tid < 12) cpa16(&pstage[4 * tid], p + ((size_t)(b * TSTEPS + t - 1)) * NSC + 4 * tid);
            cpcommit();
        }
        if (wid == 0) {
            const int col = lane & 15;
            float a[16];
#pragma unroll
            for (int i = 0; i < 16; ++i)
                a[i] = (i >= col) ? Qts[(NS + i) * SQ + NS + col]
                                  : Qts[(NS + col) * SQ + NS + i];
#pragma unroll
            for (int pv = 0; pv < 16; ++pv) {
                float piv = __shfl_sync(0xffffffffu, a[pv], pv);
                float pinv = __frcp_rn(piv);
                float cp[16];
#pragma unroll
                for (int i = 0; i < 16; ++i) cp[i] = __shfl_sync(0xffffffffu, a[i], pv);
                float rp = a[pv] * pinv;
#pragma unroll
                for (int i = 0; i < 16; ++i) if (i != pv) a[i] = fmaf(-cp[i], rp, a[i]);
                a[pv] = rp;
                if (lane == pv) {
#pragma unroll
                    for (int i = 0; i < 16; ++i) a[i] = (i == pv) ? pinv : -cp[i] * pinv;
                }
            }
            if (lane < 16) {
#pragma unroll
                for (int i = 0; i < 16; ++i) Qinv[i * SX + lane] = a[i];
            }
        } else if (wid == 1) {
            float t0 = c1s[lane] * (w2[lane] + vs[lane]);
#pragma unroll
            for (int s = 16; s; s >>= 1) t0 += __shfl_xor_sync(0xffffffffu, t0, s);
            if (lane == 0) sred_c1 = t0;
        }
        __syncthreads();

        // --- Phase D1: K = -Qinv Qux ; k = -Qinv qu (ld128) ---
        {
            const int r0 = 2 * wid, r1 = r0 + 1;
            u64 aK0 = 0, aK1 = 0, ak0 = 0, ak1 = 0;
            const float* qx = &QuxT[lane * SX];
            const float* q0p = &Qinv[r0 * SX];
            const float* q1p = &Qinv[r1 * SX];
            const float* qup = &qts[NS];
#pragma unroll
            for (int kp = 0; kp < 4; ++kp) {
                u64 x0, x1, qa, qb, qc, qd, qe, qf;
                ld128(qx + 4 * kp, x0, x1);
                ld128(q0p + 4 * kp, qa, qb);
                ld128(q1p + 4 * kp, qc, qd);
                ld128(qup + 4 * kp, qe, qf);
                aK0 = ffma2(qa, x0, aK0); aK0 = ffma2(qb, x1, aK0);
                aK1 = ffma2(qc, x0, aK1); aK1 = ffma2(qd, x1, aK1);
                ak0 = ffma2(qa, qe, ak0); ak0 = ffma2(qb, qf, ak0);
                ak1 = ffma2(qc, qe, ak1); ak1 = ffma2(qd, qf, ak1);
            }
            float K0 = -lohi(aK0), K1 = -lohi(aK1);
            KT[lane * SX + r0] = K0; KT[lane * SX + r1] = K1;
            size_t gb = ((size_t)t * NBATCH + b) * NC;
            g_K[(gb + r0) * NS + lane] = K0;
            g_K[(gb + r1) * NS + lane] = K1;
            if (lane == 0) {
                float k0 = -lohi(ak0), k1 = -lohi(ak1);
                kts[r0] = k0; kts[r1] = k1;
                g_k[gb + r0] = k0; g_k[gb + r1] = k1;
                sred[wid] = k0 * qts[NS + r0] + k1 * qts[NS + r1];
            }
        }
        __syncthreads();

        // --- Phase D2 (lower tiles): V' = Qxx + Qxu K ; v' ; s += ---
        if (tid == 0) {
            float qk = sred[0] + sred[1] + sred[2] + sred[3]
                     + sred[4] + sred[5] + sred[6] + sred[7];
            s_sh += 0.5f * (sred_c1 + qk);
        }
        if (lowB) {
            const int i0 = 2 * ty, i1 = i0 + 1, j0 = 2 * tx, j1 = j0 + 1;
            u64 a00 = pklo(Qts[i0 * SQ + j0]);
            u64 a01 = pklo((tx == ty) ? Qts[j1 * SQ + i0] : Qts[i0 * SQ + j1]);
            u64 a10 = pklo(Qts[i1 * SQ + j0]);
            u64 a11 = pklo(Qts[i1 * SQ + j1]);
            const float* x0p = &QuxT[i0 * SX];
            const float* x1p = &QuxT[i1 * SX];
            const float* kc0 = &KT[j0 * SX];
            const float* kc1 = &KT[j1 * SX];
#pragma unroll
            for (int kp = 0; kp < 4; ++kp) {
                u64 k0a, k0b, k1a, k1b, xa, xb, xc, xd;
                ld128(kc0 + 4 * kp, k0a, k0b);
                ld128(kc1 + 4 * kp, k1a, k1b);
                ld128(x0p + 4 * kp, xa, xb);
                ld128(x1p + 4 * kp, xc, xd);
                a00 = ffma2(xa, k0a, a00); a00 = ffma2(xb, k0b, a00);
                a01 = ffma2(xa, k1a, a01); a01 = ffma2(xb, k1b, a01);
                a10 = ffma2(xc, k0a, a10); a10 = ffma2(xd, k0b, a10);
                a11 = ffma2(xc, k1a, a11); a11 = ffma2(xd, k1b, a11);
            }
            float v00 = lohi(a00), v01 = lohi(a01), v10 = lohi(a10), v11 = lohi(a11);
            Vs[i0 * SF + j0] = v00; Vs[i0 * SF + j1] = v01;
            Vs[i1 * SF + j0] = v10; Vs[i1 * SF + j1] = v11;
            if (tx < ty) {
                Vs[j0 * SF + i0] = v00; Vs[j1 * SF + i0] = v01;
                Vs[j0 * SF + i1] = v10; Vs[j1 * SF + i1] = v11;
            }
        }
        if (tid < NS) {
            u64 acc = pklo(qts[tid]);
            const float* qr = &QuxT[tid * SX];
#pragma unroll
            for (int kp = 0; kp < 8; ++kp) acc = ffma2(ld64(qr + 2 * kp), ld64(&kts[2 * kp]), acc);
            vs[tid] = lohi(acc);
        }
        __syncthreads();
    }

    // --- Final: cost = 0.5 x0'V0 x0 + v0.x0 + s ---
    if (wid == 0) {
        u64 acc = 0;
        const float* vr = &Vs[lane * SF];
#pragma unroll
        for (int kp = 0; kp < 16; ++kp)
            acc = ffma2(ld64(vr + 2 * kp), ld64(&x0s[2 * kp]), acc);
        float ri = 0.5f * lohi(acc) + vs[lane];
        float ti = x0s[lane] * ri;
#pragma unroll
        for (int s = 16; s; s >>= 1) ti += __shfl_xor_sync(0xffffffffu, ti, s);
        if (lane == 0) out[cBase + b] = ti + s_sh;
    }
}

// ---------------------------------------------------------------------------
// Forward rollout. One CTA per batch, 256 threads, K triple-buffered. (= R7)
// ---------------------------------------------------------------------------
__global__ __launch_bounds__(256, 4)
void lqr_fwd_kernel(const float* __restrict__ A, const float* __restrict__ Bm,
                    const float* __restrict__ c1, const float* __restrict__ x_init,
                    float* __restrict__ out)
{
    __shared__ __align__(16) float Ksh[3][NC * NS];
    __shared__ __align__(16) float kall[TSTEPS * NC];
    __shared__ float As[NS * 33];
    __shared__ float Bs[NS * 17];
    __shared__ float c1s[NS];
    __shared__ float xu[2][NSC];

    const int b = blockIdx.x, tid = threadIdx.x;
    const size_t uBase = (size_t)NBATCH * TSTEPS * NS;

    for (int o = tid; o < NS * NS; o += 256) As[(o >> 5) * 33 + (o & 31)] = A[b * NS * NS + o];
    for (int o = tid; o < NS * NC; o += 256) Bs[(o >> 4) * 17 + (o & 15)] = Bm[b * NS * NC + o];
    if (tid < NS) { c1s[tid] = c1[b * NS + tid]; xu[0][tid] = x_init[b * NS + tid]; }

    for (int o = tid; o < 512; o += 256) {
        int t = o >> 2, ch = o & 3;
        cpa16(&kall[4 * o], g_k + ((size_t)t * NBATCH + b) * NC + 4 * ch);
    }
    if (tid < 128) cpa16(&Ksh[0][4 * tid], g_K + (size_t)b * NC * NS + 4 * tid);
    cpcommit();
    if (tid < 128) cpa16(&Ksh[1][4 * tid], g_K + ((size_t)NBATCH + b) * NC * NS + 4 * tid);
    cpcommit();

    for (int t = 0; t < TSTEPS; ++t) {
        const int cur = t & 1, nxt = cur ^ 1;
        const int c3 = t % 3;

        cpwait1();
        __syncthreads();

        {
            int c = tid >> 4, s = tid & 15;
            const float* Kc = &Ksh[c3][c * NS];
            float part = Kc[s] * xu[cur][s] + Kc[16 + s] * xu[cur][16 + s];
#pragma unroll
            for (int m = 8; m; m >>= 1) part += __shfl_xor_sync(0xffffffffu, part, m, 16);
            if (s == 0) {
                float u = part + kall[t * NC + c];
                xu[cur][NS + c] = u;
                out[uBase + (size_t)(b * TSTEPS + t) * NC + c] = u;
            }
        }
        if (tid >= 64 && tid < 96)
            out[(size_t)(b * TSTEPS + t) * NS + (tid - 64)] = xu[cur][tid - 64];
        __syncthreads();

        if (tid < NS) {
            float acc = c1s[tid];
#pragma unroll
            for (int k = 0; k < NS; ++k) acc = fmaf(As[tid * 33 + k], xu[cur][k], acc);
#pragma unroll
            for (int k = 0; k < NC; ++k) acc = fmaf(Bs[tid * 17 + k], xu[cur][NS + k], acc);
            xu[nxt][tid] = acc;
        }

        if (t + 2 < TSTEPS && tid < 128)
            cpa16(&Ksh[(t + 2) % 3][4 * tid],
                  g_K + ((size_t)(t + 2) * NBATCH + b) * NC * NS + 4 * tid);
        cpcommit();
        __syncthreads();
    }
}

// ---------------------------------------------------------------------------
extern "C" void kernel_launch(void* const* d_in, const int* in_sizes, int n_in,
                              void* d_out, int out_size)
{
    const float* x_init = (const float*)d_in[0];
    const float* Q      = (const float*)d_in[1];
    const float* p      = (const float*)d_in[2];
    const float* A      = (const float*)d_in[3];
    const float* Bm     = (const float*)d_in[4];
    const float* c1     = (const float*)d_in[5];
    float* out = (float*)d_out;

    lqr_dummy_kernel<<<1, 32>>>();
    lqr_bwd_kernel<<<NBATCH, 256>>>(Q, p, A, Bm, c1, x_init, out);
    lqr_fwd_kernel<<<NBATCH, 256>>>(A, Bm, c1, x_init, out);
    lqr_dummy_kernel<<<1, 32>>>();
}

// round 10
// speedup vs baseline: 1.1030x; 1.1030x over previous
#include <cuda_runtime.h>
#include <cstdint>
#include <cmath>

#define NBATCH 512
#define TSTEPS 128
#define NS 32
#define NC 16
#define NSC 48
typedef unsigned long long u64;

__device__ float g_K[(size_t)TSTEPS * NBATCH * NC * NS];
__device__ float g_k[(size_t)TSTEPS * NBATCH * NC];

__device__ __forceinline__ u64 ffma2(u64 a, u64 b, u64 c) {
    u64 d; asm("fma.rn.f32x2 %0,%1,%2,%3;" : "=l"(d) : "l"(a), "l"(b), "l"(c)); return d;
}
__device__ __forceinline__ float lohi(u64 v) {
    float lo, hi; asm("mov.b64 {%0,%1},%2;" : "=f"(lo), "=f"(hi) : "l"(v)); return lo + hi;
}
__device__ __forceinline__ u64 pklo(float lo) {
    u64 d; asm("mov.b64 %0,{%1,%2};" : "=l"(d) : "f"(lo), "f"(0.0f)); return d;
}
__device__ __forceinline__ u64 ld64(const float* p) { return *reinterpret_cast<const u64*>(p); }
__device__ __forceinline__ void cpa16(void* s, const void* g) {
    unsigned sa = (unsigned)__cvta_generic_to_shared(s);
    asm volatile("cp.async.ca.shared.global [%0], [%1], 16;" :: "r"(sa), "l"(g));
}
__device__ __forceinline__ void cpcommit() { asm volatile("cp.async.commit_group;"); }
__device__ __forceinline__ void cpwait0() { asm volatile("cp.async.wait_group 0;"); }
__device__ __forceinline__ void cpwait1() { asm volatile("cp.async.wait_group 1;"); }

#define SF 34
#define SQ 50
#define SX 18

// ---------------------------------------------------------------------------
// Backward Riccati pass + analytic cost. One CTA per batch, 256 threads.
// Compacted-triangular phase B and D2 (threads 0-135), qt/v' on freed warps.
// ---------------------------------------------------------------------------
__global__ __launch_bounds__(256, 4)
void lqr_bwd_kernel(const float* __restrict__ Q, const float* __restrict__ p,
                    const float* __restrict__ A, const float* __restrict__ Bm,
                    const float* __restrict__ c1, const float* __restrict__ x_init,
                    float* __restrict__ out)
{
    __shared__ __align__(16) float FkT[NSC * SF];     // FkT[j][k] = F[k][j]
    __shared__ __align__(16) float WkT[NSC * SF];     // WkT[j][k] = (V F)[k][j]
    __shared__ __align__(16) float Vs[NS * SF];       // V row-major (symmetric, full)
    __shared__ __align__(16) float Qts[NSC * SQ];     // Qt (lower tiles valid)
    __shared__ __align__(16) float Qstage[NSC * NSC]; // raw Q[t] staged via cp.async
    __shared__ __align__(16) float QuxT[NS * SX];     // QuxT[j][u] = Qux[u][j]
    __shared__ __align__(16) float Qinv[NC * SX];
    __shared__ __align__(16) float KT[NS * SX];       // KT[j][r] = K[r][j]
    __shared__ __align__(16) float qts[NSC + 2];
    __shared__ __align__(16) float kts[NC];
    __shared__ __align__(16) float w2[NS];
    __shared__ __align__(16) float vs[NS];
    __shared__ __align__(16) float c1s[NS];
    __shared__ __align__(16) float x0s[NS];
    __shared__ float sred[8];
    __shared__ float sred_c1;
    __shared__ float s_sh;

    const int b = blockIdx.x, tid = threadIdx.x;
    const int lane = tid & 31, wid = tid >> 5;
    const int ty = tid >> 4, tx = tid & 15;
    const size_t cBase = (size_t)NBATCH * TSTEPS * NS + (size_t)NBATCH * TSTEPS * NC;

    // compacted triangular tile coordinates (constant over the t-loop)
    int bty = 0, btx = 0;
    const bool tri = (tid < 136);
    if (tri) {
        bty = (int)((sqrtf(8.0f * (float)tid + 1.0f) - 1.0f) * 0.5f);
        while ((bty + 1) * (bty + 2) / 2 <= tid) ++bty;
        while (bty * (bty + 1) / 2 > tid) --bty;
        btx = tid - bty * (bty + 1) / 2;   // 0 <= btx <= bty <= 15
    }
    const bool qtT = (tid >= 160 && tid < 208);   // qt workers (48)
    const int qtj = tid - 160;
    const bool vpT = (tid >= 160 && tid < 192);   // v' workers (32)
    const int vpi = tid - 160;

    for (int o = tid; o < NS * NSC; o += 256) {
        int j = o >> 5, k = o & 31;
        FkT[j * SF + k] = (j < NS) ? A[b * NS * NS + k * NS + j]
                                   : Bm[b * NS * NC + k * NC + (j - NS)];
    }
    if (tid < NS) {
        c1s[tid] = c1[b * NS + tid];
        x0s[tid] = x_init[b * NS + tid];
        vs[tid] = 0.f;
    }
    if (tid == 0) s_sh = 0.f;
    for (int o = tid; o < NS * SF; o += 256) Vs[o] = 0.f;

    // stage Q[t=127]
    {
        const float* Qg = Q + ((size_t)(b * TSTEPS + TSTEPS - 1)) * (NSC * NSC);
        for (int o = tid; o < 576; o += 256) cpa16(&Qstage[4 * o], Qg + 4 * o);
        cpcommit();
    }
    __syncthreads();

    const float c1l = c1s[lane];

    for (int t = TSTEPS - 1; t >= 0; --t) {
        const float* pg = p + ((size_t)(b * TSTEPS + t)) * NSC;
        float preg = qtT ? pg[qtj] : 0.f;

        // --- Phase A: W = V*F (2x3 tiles, 16x16 grid) ; w2 = v + V c1 ---
        {
            u64 a00 = 0, a01 = 0, a02 = 0, a10 = 0, a11 = 0, a12 = 0;
            const float* vr0 = &Vs[(2 * ty) * SF];
            const float* vr1 = vr0 + SF;
            const float* f0 = &FkT[(3 * tx) * SF];
            const float* f1 = f0 + SF;
            const float* f2 = f1 + SF;
#pragma unroll
            for (int kp = 0; kp < 16; ++kp) {
                u64 fp0 = ld64(f0 + 2 * kp), fp1 = ld64(f1 + 2 * kp), fp2 = ld64(f2 + 2 * kp);
                u64 v0 = ld64(vr0 + 2 * kp), v1 = ld64(vr1 + 2 * kp);
                a00 = ffma2(v0, fp0, a00); a01 = ffma2(v0, fp1, a01); a02 = ffma2(v0, fp2, a02);
                a10 = ffma2(v1, fp0, a10); a11 = ffma2(v1, fp1, a11); a12 = ffma2(v1, fp2, a12);
            }
            WkT[(3 * tx) * SF + 2 * ty] = lohi(a00);
            WkT[(3 * tx + 1) * SF + 2 * ty] = lohi(a01);
            WkT[(3 * tx + 2) * SF + 2 * ty] = lohi(a02);
            WkT[(3 * tx) * SF + 2 * ty + 1] = lohi(a10);
            WkT[(3 * tx + 1) * SF + 2 * ty + 1] = lohi(a11);
            WkT[(3 * tx + 2) * SF + 2 * ty + 1] = lohi(a12);
        }
#pragma unroll
        for (int r = 0; r < 4; ++r) {
            int i = 4 * wid + r;
            float t0 = Vs[i * SF + lane] * c1l;
#pragma unroll
            for (int s = 16; s; s >>= 1) t0 += __shfl_xor_sync(0xffffffffu, t0, s);
            if (lane == 0) w2[i] = vs[i] + t0;
        }
        cpwait0();           // staged Q[t] resident
        __syncthreads();

        // --- Phase B: Qt(lower, compacted) = Qstage + F^T W ; qt concurrent ---
        if (tri) {
            u64 acc[3][3] = {{0,0,0},{0,0,0},{0,0,0}};
            const float* fr0 = &FkT[(3 * bty) * SF];
            const float* fr1 = fr0 + SF;
            const float* fr2 = fr1 + SF;
            const float* wc0 = &WkT[(3 * btx) * SF];
            const float* wc1 = wc0 + SF;
            const float* wc2 = wc1 + SF;
#pragma unroll
            for (int kp = 0; kp < 16; ++kp) {
                u64 w0 = ld64(wc0 + 2 * kp), w1 = ld64(wc1 + 2 * kp), wq = ld64(wc2 + 2 * kp);
                u64 fa = ld64(fr0 + 2 * kp), fb = ld64(fr1 + 2 * kp), fc = ld64(fr2 + 2 * kp);
                acc[0][0] = ffma2(fa, w0, acc[0][0]); acc[0][1] = ffma2(fa, w1, acc[0][1]); acc[0][2] = ffma2(fa, wq, acc[0][2]);
                acc[1][0] = ffma2(fb, w0, acc[1][0]); acc[1][1] = ffma2(fb, w1, acc[1][1]); acc[1][2] = ffma2(fb, wq, acc[1][2]);
                acc[2][0] = ffma2(fc, w0, acc[2][0]); acc[2][1] = ffma2(fc, w1, acc[2][1]); acc[2][2] = ffma2(fc, wq, acc[2][2]);
            }
#pragma unroll
            for (int r = 0; r < 3; ++r)
#pragma unroll
                for (int c = 0; c < 3; ++c) {
                    int i = 3 * bty + r, j = 3 * btx + c;
                    float val = Qstage[i * NSC + j] + lohi(acc[r][c]);
                    Qts[i * SQ + j] = val;
                    if (i >= NS && j < NS) QuxT[j * SX + (i - NS)] = val;
                }
        } else if (qtT) {
            u64 acc = 0;
            const float* fr = &FkT[qtj * SF];
#pragma unroll
            for (int kp = 0; kp < 16; ++kp) acc = ffma2(ld64(fr + 2 * kp), ld64(&w2[2 * kp]), acc);
            qts[qtj] = preg + lohi(acc);
        }
        __syncthreads();

        // --- Phase C: prefetch Q[t-1] ; warp0 inverts Quu ; warp1 c1-dot ---
        if (t > 0) {
            const float* Qg = Q + ((size_t)(b * TSTEPS + t - 1)) * (NSC * NSC);
            for (int o = tid; o < 576; o += 256) cpa16(&Qstage[4 * o], Qg + 4 * o);
            cpcommit();
        }
        if (wid == 0) {
            const int col = lane & 15;
            float a[16];
#pragma unroll
            for (int i = 0; i < 16; ++i)
                a[i] = (i >= col) ? Qts[(NS + i) * SQ + NS + col]
                                  : Qts[(NS + col) * SQ + NS + i];
#pragma unroll
            for (int pv = 0; pv < 16; ++pv) {
                float piv = __shfl_sync(0xffffffffu, a[pv], pv);
                float pinv = __frcp_rn(piv);
                float cp[16];
#pragma unroll
                for (int i = 0; i < 16; ++i) cp[i] = __shfl_sync(0xffffffffu, a[i], pv);
                float rp = a[pv] * pinv;
#pragma unroll
                for (int i = 0; i < 16; ++i) if (i != pv) a[i] = fmaf(-cp[i], rp, a[i]);
                a[pv] = rp;
                if (lane == pv) {
#pragma unroll
                    for (int i = 0; i < 16; ++i) a[i] = (i == pv) ? pinv : -cp[i] * pinv;
                }
            }
            if (lane < 16) {
#pragma unroll
                for (int i = 0; i < 16; ++i) Qinv[i * SX + lane] = a[i];
            }
        } else if (wid == 1) {
            float t0 = c1s[lane] * (w2[lane] + vs[lane]);
#pragma unroll
            for (int s = 16; s; s >>= 1) t0 += __shfl_xor_sync(0xffffffffu, t0, s);
            if (lane == 0) sred_c1 = t0;
        }
        __syncthreads();

        // --- Phase D1: K = -Qinv Qux ; k = -Qinv qu ---
        {
            const int r0 = 2 * wid, r1 = r0 + 1;
            u64 aK0 = 0, aK1 = 0, ak0 = 0, ak1 = 0;
            const float* qx = &QuxT[lane * SX];
#pragma unroll
            for (int kp = 0; kp < 8; ++kp) {
                u64 x = ld64(qx + 2 * kp);
                u64 q0 = ld64(&Qinv[r0 * SX + 2 * kp]);
                u64 q1 = ld64(&Qinv[r1 * SX + 2 * kp]);
                u64 qu = ld64(&qts[NS + 2 * kp]);
                aK0 = ffma2(q0, x, aK0); aK1 = ffma2(q1, x, aK1);
                ak0 = ffma2(q0, qu, ak0); ak1 = ffma2(q1, qu, ak1);
            }
            float K0 = -lohi(aK0), K1 = -lohi(aK1);
            KT[lane * SX + r0] = K0; KT[lane * SX + r1] = K1;
            size_t gb = ((size_t)t * NBATCH + b) * NC;
            g_K[(gb + r0) * NS + lane] = K0;
            g_K[(gb + r1) * NS + lane] = K1;
            if (lane == 0) {
                float k0 = -lohi(ak0), k1 = -lohi(ak1);
                kts[r0] = k0; kts[r1] = k1;
                g_k[gb + r0] = k0; g_k[gb + r1] = k1;
                sred[wid] = k0 * qts[NS + r0] + k1 * qts[NS + r1];
            }
        }
        __syncthreads();

        // --- Phase D2 (compacted lower): V' = Qxx + Qxu K ; v' concurrent ---
        if (tid == 0) {
            float qk = sred[0] + sred[1] + sred[2] + sred[3]
                     + sred[4] + sred[5] + sred[6] + sred[7];
            s_sh += 0.5f * (sred_c1 + qk);
        }
        if (tri) {
            const int i0 = 2 * bty, i1 = i0 + 1, j0 = 2 * btx, j1 = j0 + 1;
            u64 a00 = pklo(Qts[i0 * SQ + j0]);
            u64 a01 = pklo((btx == bty) ? Qts[j1 * SQ + i0] : Qts[i0 * SQ + j1]);
            u64 a10 = pklo(Qts[i1 * SQ + j0]);
            u64 a11 = pklo(Qts[i1 * SQ + j1]);
            const float* x0p = &QuxT[i0 * SX];
            const float* x1p = &QuxT[i1 * SX];
            const float* kc0 = &KT[j0 * SX];
            const float* kc1 = &KT[j1 * SX];
#pragma unroll
            for (int kp = 0; kp < 8; ++kp) {
                u64 k0 = ld64(kc0 + 2 * kp), k1 = ld64(kc1 + 2 * kp);
                u64 x0 = ld64(x0p + 2 * kp), x1 = ld64(x1p + 2 * kp);
                a00 = ffma2(x0, k0, a00); a01 = ffma2(x0, k1, a01);
                a10 = ffma2(x1, k0, a10); a11 = ffma2(x1, k1, a11);
            }
            float v00 = lohi(a00), v01 = lohi(a01), v10 = lohi(a10), v11 = lohi(a11);
            Vs[i0 * SF + j0] = v00; Vs[i0 * SF + j1] = v01;
            Vs[i1 * SF + j0] = v10; Vs[i1 * SF + j1] = v11;
            if (btx < bty) {
                Vs[j0 * SF + i0] = v00; Vs[j1 * SF + i0] = v01;
                Vs[j0 * SF + i1] = v10; Vs[j1 * SF + i1] = v11;
            }
        } else if (vpT) {
            u64 acc = pklo(qts[vpi]);
            const float* qr = &QuxT[vpi * SX];
#pragma unroll
            for (int kp = 0; kp < 8; ++kp) acc = ffma2(ld64(qr + 2 * kp), ld64(&kts[2 * kp]), acc);
            vs[vpi] = lohi(acc);
        }
        __syncthreads();
    }

    // --- Final: cost = 0.5 x0'V0 x0 + v0.x0 + s ---
    if (wid == 0) {
        u64 acc = 0;
        const float* vr = &Vs[lane * SF];
#pragma unroll
        for (int kp = 0; kp < 16; ++kp)
            acc = ffma2(ld64(vr + 2 * kp), ld64(&x0s[2 * kp]), acc);
        float ri = 0.5f * lohi(acc) + vs[lane];
        float ti = x0s[lane] * ri;
#pragma unroll
        for (int s = 16; s; s >>= 1) ti += __shfl_xor_sync(0xffffffffu, ti, s);
        if (lane == 0) out[cBase + b] = ti + s_sh;
    }
}

// ---------------------------------------------------------------------------
// Forward rollout. One CTA per batch, 256 threads, K triple-buffered. (= R7)
// ---------------------------------------------------------------------------
__global__ __launch_bounds__(256, 4)
void lqr_fwd_kernel(const float* __restrict__ A, const float* __restrict__ Bm,
                    const float* __restrict__ c1, const float* __restrict__ x_init,
                    float* __restrict__ out)
{
    __shared__ __align__(16) float Ksh[3][NC * NS];
    __shared__ __align__(16) float kall[TSTEPS * NC];
    __shared__ float As[NS * 33];
    __shared__ float Bs[NS * 17];
    __shared__ float c1s[NS];
    __shared__ float xu[2][NSC];

    const int b = blockIdx.x, tid = threadIdx.x;
    const size_t uBase = (size_t)NBATCH * TSTEPS * NS;

    for (int o = tid; o < NS * NS; o += 256) As[(o >> 5) * 33 + (o & 31)] = A[b * NS * NS + o];
    for (int o = tid; o < NS * NC; o += 256) Bs[(o >> 4) * 17 + (o & 15)] = Bm[b * NS * NC + o];
    if (tid < NS) { c1s[tid] = c1[b * NS + tid]; xu[0][tid] = x_init[b * NS + tid]; }

    for (int o = tid; o < 512; o += 256) {
        int t = o >> 2, ch = o & 3;
        cpa16(&kall[4 * o], g_k + ((size_t)t * NBATCH + b) * NC + 4 * ch);
    }
    if (tid < 128) cpa16(&Ksh[0][4 * tid], g_K + (size_t)b * NC * NS + 4 * tid);
    cpcommit();
    if (tid < 128) cpa16(&Ksh[1][4 * tid], g_K + ((size_t)NBATCH + b) * NC * NS + 4 * tid);
    cpcommit();

    for (int t = 0; t < TSTEPS; ++t) {
        const int cur = t & 1, nxt = cur ^ 1;
        const int c3 = t % 3;

        cpwait1();
        __syncthreads();

        {
            int c = tid >> 4, s = tid & 15;
            const float* Kc = &Ksh[c3][c * NS];
            float part = Kc[s] * xu[cur][s] + Kc[16 + s] * xu[cur][16 + s];
#pragma unroll
            for (int m = 8; m; m >>= 1) part += __shfl_xor_sync(0xffffffffu, part, m, 16);
            if (s == 0) {
                float u = part + kall[t * NC + c];
                xu[cur][NS + c] = u;
                out[uBase + (size_t)(b * TSTEPS + t) * NC + c] = u;
            }
        }
        if (tid >= 64 && tid < 96)
            out[(size_t)(b * TSTEPS + t) * NS + (tid - 64)] = xu[cur][tid - 64];
        __syncthreads();

        if (tid < NS) {
            float acc = c1s[tid];
#pragma unroll
            for (int k = 0; k < NS; ++k) acc = fmaf(As[tid * 33 + k], xu[cur][k], acc);
#pragma unroll
            for (int k = 0; k < NC; ++k) acc = fmaf(Bs[tid * 17 + k], xu[cur][NS + k], acc);
            xu[nxt][tid] = acc;
        }

        if (t + 2 < TSTEPS && tid < 128)
            cpa16(&Ksh[(t + 2) % 3][4 * tid],
                  g_K + ((size_t)(t + 2) * NBATCH + b) * NC * NS + 4 * tid);
        cpcommit();
        __syncthreads();
    }
}

// ---------------------------------------------------------------------------
extern "C" void kernel_launch(void* const* d_in, const int* in_sizes, int n_in,
                              void* d_out, int out_size)
{
    const float* x_init = (const float*)d_in[0];
    const float* Q      = (const float*)d_in[1];
    const float* p      = (const float*)d_in[2];
    const float* A      = (const float*)d_in[3];
    const float* Bm     = (const float*)d_in[4];
    const float* c1     = (const float*)d_in[5];
    float* out = (float*)d_out;

    lqr_bwd_kernel<<<NBATCH, 256>>>(Q, p, A, Bm, c1, x_init, out);
    lqr_fwd_kernel<<<NBATCH, 256>>>(A, Bm, c1, x_init, out);
}